// round 10
// baseline (speedup 1.0000x reference)
#include <cuda_runtime.h>
#include <cuda_bf16.h>

#define BB 4096
#define TT 365
#define HORIZON 7
#define ROWS 32
#define NCTA (BB / ROWS)     // 128
#define NTH 512

// ---- SMEM byte offsets (weight arrays 128B-row pitch, SW128 swizzled) ----
#define OFF_W0H   0u          // Whh0 hi   [256 cols][64 k] bf16
#define OFF_W0L   32768u      // Whh0 lo
#define OFF_W1AH  65536u      // Wih1 hi   (L1, k from h0)
#define OFF_W1AL  98304u
#define OFF_W1BH  131072u     // Whh1 hi   (L1, k from h1)
#define OFF_W1BL  163840u
#define OFF_AH0   196608u     // h0[buf 2][split 2]: 32x64 bf16 = 4096B each
#define OFF_AH1   212992u     // h1[buf 2][split 2]
#define OFF_B0P   229376u     // permuted fp32 bias b0 [256]
#define OFF_B1P   230400u     // permuted fp32 bias b1 [256]
#define OFF_WIP   231424u     // permuted fp32 Wih0   [256]
#define SMEM_BYTES 232448u    // == sm_103a opt-in cap

// decoder FC scratch (per-CTA slices of device globals; no allocation)
__device__ float g_pp[NCTA][8][32];
__device__ float g_fb[NCTA][32];

__device__ __forceinline__ unsigned swz(unsigned o) { return o ^ ((o >> 3) & 0x70u); }

__device__ __forceinline__ void ldsm4(unsigned &r0, unsigned &r1, unsigned &r2, unsigned &r3,
                                      unsigned a) {
    asm volatile("ldmatrix.sync.aligned.m8n8.x4.shared.b16 {%0,%1,%2,%3}, [%4];"
                 : "=r"(r0), "=r"(r1), "=r"(r2), "=r"(r3) : "r"(a));
}

__device__ __forceinline__ void mma16816(float d[4], unsigned a0, unsigned a1, unsigned a2,
                                         unsigned a3, unsigned b0, unsigned b1) {
    asm volatile("mma.sync.aligned.m16n8k16.row.col.f32.bf16.bf16.f32 "
                 "{%0,%1,%2,%3},{%4,%5,%6,%7},{%8,%9},{%0,%1,%2,%3};"
                 : "+f"(d[0]), "+f"(d[1]), "+f"(d[2]), "+f"(d[3])
                 : "r"(a0), "r"(a1), "r"(a2), "r"(a3), "r"(b0), "r"(b1));
}

__device__ __forceinline__ float sigm(float v) {
    return __fdividef(1.f, 1.f + __expf(-v));
}
__device__ __forceinline__ float tanh_(float v) {
    float a = fabsf(v);
    float e = __expf(-2.f * a);
    float r = __fdividef(1.f - e, 1.f + e);
    return copysignf(r, v);
}

// gates[4 ntiles] += A(32x64 split) @ W(64x256 split), 3-product bf16 split.
__device__ __forceinline__ void gemm16(float acc[4][4], unsigned sb,
                                       unsigned aH, unsigned aL,
                                       unsigned wH, unsigned wL,
                                       unsigned raOff, unsigned cbOff) {
    #pragma unroll
    for (int ks = 0; ks < 4; ++ks) {
        unsigned ah0, ah1, ah2, ah3, al0, al1, al2, al3;
        ldsm4(ah0, ah1, ah2, ah3, sb + aH + swz(raOff + ks * 32));
        ldsm4(al0, al1, al2, al3, sb + aL + swz(raOff + ks * 32));
        #pragma unroll
        for (int tp = 0; tp < 2; ++tp) {
            unsigned bh0, bh1, bh2, bh3, bl0, bl1, bl2, bl3;
            ldsm4(bh0, bh1, bh2, bh3, sb + wH + swz(cbOff + tp * 2048 + ks * 32));
            ldsm4(bl0, bl1, bl2, bl3, sb + wL + swz(cbOff + tp * 2048 + ks * 32));
            mma16816(acc[2 * tp],     ah0, ah1, ah2, ah3, bh0, bh1);
            mma16816(acc[2 * tp],     ah0, ah1, ah2, ah3, bl0, bl1);
            mma16816(acc[2 * tp],     al0, al1, al2, al3, bh0, bh1);
            mma16816(acc[2 * tp + 1], ah0, ah1, ah2, ah3, bh2, bh3);
            mma16816(acc[2 * tp + 1], ah0, ah1, ah2, ah3, bl2, bl3);
            mma16816(acc[2 * tp + 1], al0, al1, al2, al3, bh2, bh3);
        }
    }
}

// Split LSTM cell: even lane (ifh) computes tiles 0,1; odd lane tiles 2,3.
// 12 shfl total; both lanes end with the FULL hv[4][2]. cst[4] = owned tiles only.
__device__ __forceinline__ void cellq2(const float acc[4][4], float cst[4],
                                       float hv[4][2], int ifh) {
    float recv[2][4];
    #pragma unroll
    for (int tt = 0; tt < 2; ++tt)
        #pragma unroll
        for (int e = 0; e < 4; ++e) {
            float send = ifh ? acc[2 + tt][e] : acc[tt][e];
            recv[tt][e] = __shfl_xor_sync(0xFFFFFFFFu, send, 1);
        }
    float hwon[2][2];
    #pragma unroll
    for (int tt = 0; tt < 2; ++tt) {
        int t = ifh ? tt : 2 + tt;
        float gi = ifh ? acc[t][0] : recv[tt][0];
        float gf = ifh ? acc[t][1] : recv[tt][1];
        float gg = ifh ? recv[tt][0] : acc[t][0];
        float go = ifh ? recv[tt][1] : acc[t][1];
        float cn = sigm(gf) * cst[2 * tt] + sigm(gi) * tanh_(gg);
        cst[2 * tt] = cn;
        hwon[tt][0] = sigm(go) * tanh_(cn);
        gi = ifh ? acc[t][2] : recv[tt][2];
        gf = ifh ? acc[t][3] : recv[tt][3];
        gg = ifh ? recv[tt][2] : acc[t][2];
        go = ifh ? recv[tt][3] : acc[t][3];
        cn = sigm(gf) * cst[2 * tt + 1] + sigm(gi) * tanh_(gg);
        cst[2 * tt + 1] = cn;
        hwon[tt][1] = sigm(go) * tanh_(cn);
    }
    #pragma unroll
    for (int tt = 0; tt < 2; ++tt)
        #pragma unroll
        for (int r = 0; r < 2; ++r) {
            float got = __shfl_xor_sync(0xFFFFFFFFu, hwon[tt][r], 1);
            if (ifh) { hv[tt][r] = hwon[tt][r]; hv[2 + tt][r] = got; }
            else     { hv[tt][r] = got;         hv[2 + tt][r] = hwon[tt][r]; }
        }
}

// bf16 hi/lo split writeback of h (writer lanes only: one lane per pair).
__device__ __forceinline__ void storehq(char *smp, unsigned offH, unsigned offL,
                                        const float hv[4][2], int nb, int ug,
                                        int rA, int rB, int writer) {
    if (!writer) return;
    #pragma unroll
    for (int t = 0; t < 4; ++t) {
        int u = 2 * (nb + t) + ug;
        unsigned oA = swz((unsigned)(rA * 128 + u * 2));
        unsigned oB = swz((unsigned)(rB * 128 + u * 2));
        __nv_bfloat16 hA = __float2bfloat16(hv[t][0]);
        __nv_bfloat16 lA = __float2bfloat16(hv[t][0] - __bfloat162float(hA));
        __nv_bfloat16 hB = __float2bfloat16(hv[t][1]);
        __nv_bfloat16 lB = __float2bfloat16(hv[t][1] - __bfloat162float(hB));
        *(__nv_bfloat16 *)(smp + offH + oA) = hA;
        *(__nv_bfloat16 *)(smp + offL + oA) = lA;
        *(__nv_bfloat16 *)(smp + offH + oB) = hB;
        *(__nv_bfloat16 *)(smp + offL + oB) = lB;
    }
}

// Split-store raw fp32 weights [256 gate-rows][64 k] into gate-interleaved
// swizzled bf16 hi/lo: col c = u*4 + g, addr = swz(c*128 + k*2).
__device__ void store_w(char *smp, unsigned offH, unsigned offL, const float *__restrict__ raw) {
    for (int e = threadIdx.x; e < 256 * 64; e += NTH) {
        int R = e >> 6, k = e & 63;
        int c = (R & 63) * 4 + (R >> 6);
        float w = raw[e];
        __nv_bfloat16 hi = __float2bfloat16(w);
        __nv_bfloat16 lo = __float2bfloat16(w - __bfloat162float(hi));
        unsigned o = swz((unsigned)(c * 128 + k * 2));
        *(__nv_bfloat16 *)(smp + offH + o) = hi;
        *(__nv_bfloat16 *)(smp + offL + o) = lo;
    }
}

// Permuted fp32 bias/input-weight tables: p[c] = raw[(c&3)*64 + (c>>2)]
__device__ void store_small(char *smp, const float *__restrict__ b0,
                            const float *__restrict__ b1, const float *__restrict__ wi) {
    for (int c = threadIdx.x; c < 256; c += NTH) {
        int raw = (c & 3) * 64 + (c >> 2);
        ((float *)(smp + OFF_B0P))[c] = b0[raw];
        ((float *)(smp + OFF_B1P))[c] = b1[raw];
        ((float *)(smp + OFF_WIP))[c] = wi[raw];
    }
}

__global__ void __launch_bounds__(NTH, 1)
lstm_kernel(const float *__restrict__ x,
            const float *__restrict__ eWih0, const float *__restrict__ eWhh0,
            const float *__restrict__ eb0,
            const float *__restrict__ eWih1, const float *__restrict__ eWhh1,
            const float *__restrict__ eb1,
            const float *__restrict__ dWih0, const float *__restrict__ dWhh0,
            const float *__restrict__ db0,
            const float *__restrict__ dWih1, const float *__restrict__ dWhh1,
            const float *__restrict__ db1,
            const float *__restrict__ fcW, const float *__restrict__ fcb,
            float *__restrict__ out) {
    extern __shared__ char smem[];
    unsigned sb = (unsigned)__cvta_generic_to_shared(smem);

    const int tid = threadIdx.x;
    const int lane = tid & 31;
    const int wid = tid >> 5;
    const int mw = wid & 1;              // m-tile: rows 16mw..16mw+15
    const int nb = (wid >> 1) * 4;       // 4 n-tiles: cols 8nb..8nb+31
    const int blk = blockIdx.x;

    const int ifh = !(lane & 1);         // lane holds (i,f); partner holds (g,o)
    const int ug = (lane >> 1) & 1;      // unit-in-tile
    const int rA = mw * 16 + (lane >> 2);
    const int rB = rA + 8;
    const int bix = ((lane & 3) << 1);   // pair offset inside a tile's 8 cols

    // ldmatrix per-lane address bases (SW128-swizzled arrays, 128B row pitch)
    const unsigned raOff = (unsigned)((mw * 16 + (lane & 7) + (lane & 8)) * 128
                                      + ((lane >> 4) & 1) * 16);
    const unsigned cbOff = (unsigned)((8 * nb + (lane & 7) + 8 * ((lane >> 4) & 1)) * 128
                                      + ((lane >> 3) & 1) * 16);

    const float *b0p = (const float *)(smem + OFF_B0P);
    const float *b1p = (const float *)(smem + OFF_B1P);
    const float *wip = (const float *)(smem + OFF_WIP);

    // ---------- encoder weights ----------
    store_w(smem, OFF_W0H, OFF_W0L, eWhh0);
    store_w(smem, OFF_W1AH, OFF_W1AL, eWih1);
    store_w(smem, OFF_W1BH, OFF_W1BL, eWhh1);
    store_small(smem, eb0, eb1, eWih0);
    for (int i = tid; i < 8192; i += NTH) ((float *)(smem + OFF_AH0))[i] = 0.f;  // h bufs
    __syncthreads();

    float c0s[4], c1s[4];
    #pragma unroll
    for (int i = 0; i < 4; ++i) { c0s[i] = 0.f; c1s[i] = 0.f; }

    const float *xrA = x + (blk * 32 + rA) * TT;
    const float *xrB = x + (blk * 32 + rB) * TT;
    float xA = xrA[0], xB = xrB[0];

    // ---------- encoder: 365 steps, 2 barriers/step, hoisted Whh1 gemm ----------
    for (int t = 0; t < TT; ++t) {
        float xnA = (t + 1 < TT) ? xrA[t + 1] : 0.f;
        float xnB = (t + 1 < TT) ? xrB[t + 1] : 0.f;
        unsigned p = (unsigned)(t & 1);

        unsigned h0r = OFF_AH0 + p * 8192;
        unsigned h0w = OFF_AH0 + (p ^ 1) * 8192;
        unsigned h1r = OFF_AH1 + p * 8192;
        unsigned h1w = OFF_AH1 + (p ^ 1) * 8192;

        float acc0[4][4], acc1[4][4];
        #pragma unroll
        for (int tt = 0; tt < 4; ++tt) {
            float2 b0v = *(const float2 *)(b0p + 8 * (nb + tt) + bix);
            float2 wiv = *(const float2 *)(wip + 8 * (nb + tt) + bix);
            float2 b1v = *(const float2 *)(b1p + 8 * (nb + tt) + bix);
            acc0[tt][0] = fmaf(xA, wiv.x, b0v.x);
            acc0[tt][1] = fmaf(xA, wiv.y, b0v.y);
            acc0[tt][2] = fmaf(xB, wiv.x, b0v.x);
            acc0[tt][3] = fmaf(xB, wiv.y, b0v.y);
            acc1[tt][0] = b1v.x; acc1[tt][1] = b1v.y;
            acc1[tt][2] = b1v.x; acc1[tt][3] = b1v.y;
        }

        // pre-barrier: both prev-state gemms
        gemm16(acc0, sb, h0r, h0r + 4096, OFF_W0H, OFF_W0L, raOff, cbOff);
        gemm16(acc1, sb, h1r, h1r + 4096, OFF_W1BH, OFF_W1BL, raOff, cbOff);

        float hv[4][2];
        cellq2(acc0, c0s, hv, ifh);
        storehq(smem, h0w, h0w + 4096, hv, nb, ug, rA, rB, ifh);
        __syncthreads();                               // BAR1: h0w visible

        // post-barrier: only the Wih1 gemm + cell1
        gemm16(acc1, sb, h0w, h0w + 4096, OFF_W1AH, OFF_W1AL, raOff, cbOff);
        cellq2(acc1, c1s, hv, ifh);
        storehq(smem, h1w, h1w + 4096, hv, nb, ug, rA, rB, ifh);
        __syncthreads();                               // BAR2: h1w visible for next pre-phase

        xA = xnA; xB = xnB;
    }

    // ---------- decoder weights (BAR2 of last step ordered all encoder reads) ----------
    store_w(smem, OFF_W0H, OFF_W0L, dWhh0);
    store_w(smem, OFF_W1AH, OFF_W1AL, dWih1);
    store_w(smem, OFF_W1BH, OFF_W1BL, dWhh1);
    store_small(smem, db0, db1, dWih0);
    float fcw4[4];
    #pragma unroll
    for (int tt = 0; tt < 4; ++tt) fcw4[tt] = fcW[2 * (nb + tt) + ug];
    const float fcbv = fcb[0];
    __syncthreads();

    // ---------- decoder: 7 autoregressive steps ----------
    xA = 0.f; xB = 0.f;
    for (int s = 0; s < HORIZON; ++s) {
        unsigned p = (unsigned)((TT + s) & 1);
        unsigned h0r = OFF_AH0 + p * 8192;
        unsigned h0w = OFF_AH0 + (p ^ 1) * 8192;
        unsigned h1r = OFF_AH1 + p * 8192;
        unsigned h1w = OFF_AH1 + (p ^ 1) * 8192;

        float acc0[4][4], acc1[4][4];
        #pragma unroll
        for (int tt = 0; tt < 4; ++tt) {
            float2 b0v = *(const float2 *)(b0p + 8 * (nb + tt) + bix);
            float2 wiv = *(const float2 *)(wip + 8 * (nb + tt) + bix);
            float2 b1v = *(const float2 *)(b1p + 8 * (nb + tt) + bix);
            acc0[tt][0] = fmaf(xA, wiv.x, b0v.x);
            acc0[tt][1] = fmaf(xA, wiv.y, b0v.y);
            acc0[tt][2] = fmaf(xB, wiv.x, b0v.x);
            acc0[tt][3] = fmaf(xB, wiv.y, b0v.y);
            acc1[tt][0] = b1v.x; acc1[tt][1] = b1v.y;
            acc1[tt][2] = b1v.x; acc1[tt][3] = b1v.y;
        }
        gemm16(acc0, sb, h0r, h0r + 4096, OFF_W0H, OFF_W0L, raOff, cbOff);
        gemm16(acc1, sb, h1r, h1r + 4096, OFF_W1BH, OFF_W1BL, raOff, cbOff);

        float hv[4][2];
        cellq2(acc0, c0s, hv, ifh);
        storehq(smem, h0w, h0w + 4096, hv, nb, ug, rA, rB, ifh);
        __syncthreads();

        gemm16(acc1, sb, h0w, h0w + 4096, OFF_W1AH, OFF_W1AL, raOff, cbOff);
        cellq2(acc1, c1s, hv, ifh);
        storehq(smem, h1w, h1w + 4096, hv, nb, ug, rA, rB, ifh);

        // FC: per-lane partial over its 4 units (writer lanes), pair-sum, store
        float v0 = 0.f, v1 = 0.f;
        if (ifh) {
            #pragma unroll
            for (int tt = 0; tt < 4; ++tt) {
                v0 += hv[tt][0] * fcw4[tt];
                v1 += hv[tt][1] * fcw4[tt];
            }
        }
        v0 += __shfl_xor_sync(0xFFFFFFFFu, v0, 2);
        v1 += __shfl_xor_sync(0xFFFFFFFFu, v1, 2);
        if ((lane & 3) == 0) {
            g_pp[blk][wid >> 1][rA] = v0;
            g_pp[blk][wid >> 1][rB] = v1;
        }
        __syncthreads();
        if (tid < 32) {
            float sum = fcbv;
            #pragma unroll
            for (int j = 0; j < 8; ++j) sum += g_pp[blk][j][tid];
            out[(blk * 32 + tid) * HORIZON + s] = sum;
            g_fb[blk][tid] = sum;
        }
        __syncthreads();
        xA = g_fb[blk][rA];
        xB = g_fb[blk][rB];
    }
}

extern "C" void kernel_launch(void *const *d_in, const int *in_sizes, int n_in,
                              void *d_out, int out_size) {
    cudaFuncSetAttribute(lstm_kernel, cudaFuncAttributeMaxDynamicSharedMemorySize, SMEM_BYTES);
    lstm_kernel<<<NCTA, NTH, SMEM_BYTES>>>(
        (const float *)d_in[0],
        (const float *)d_in[1], (const float *)d_in[2], (const float *)d_in[3],
        (const float *)d_in[4], (const float *)d_in[5], (const float *)d_in[6],
        (const float *)d_in[7], (const float *)d_in[8], (const float *)d_in[9],
        (const float *)d_in[10], (const float *)d_in[11], (const float *)d_in[12],
        (const float *)d_in[13], (const float *)d_in[14],
        (float *)d_out);
}

// round 11
// speedup vs baseline: 1.4053x; 1.4053x over previous
#include <cuda_runtime.h>
#include <cuda_bf16.h>

#define BB 4096
#define TT 365
#define HORIZON 7
#define ROWS 32
#define NCTA (BB / ROWS)     // 128
#define NTH 512

// ---- SMEM byte offsets (all arrays 128B-row pitch, SW128 swizzled) ----
#define OFF_W0H   0u          // Whh0 hi   [256 cols][64 k] bf16
#define OFF_W0L   32768u      // Whh0 lo
#define OFF_W1AH  65536u      // Wih1 hi   (L1, k from h0)
#define OFF_W1AL  98304u
#define OFF_W1BH  131072u     // Whh1 hi   (L1, k from h1)
#define OFF_W1BL  163840u
#define OFF_AH0   196608u     // h0[buf 2][split 2]: 32 rows x 64 units bf16 = 4096B each
#define OFF_AH1   212992u     // h1[buf 2][split 2]
#define SMEM_BYTES 229376u

// decoder FC scratch (per-CTA slices of device globals; no allocation)
__device__ float g_pp[NCTA][8][32];
__device__ float g_fb[NCTA][32];

__device__ __forceinline__ unsigned swz(unsigned o) { return o ^ ((o >> 3) & 0x70u); }

__device__ __forceinline__ void ldsm4(unsigned &r0, unsigned &r1, unsigned &r2, unsigned &r3,
                                      unsigned a) {
    asm volatile("ldmatrix.sync.aligned.m8n8.x4.shared.b16 {%0,%1,%2,%3}, [%4];"
                 : "=r"(r0), "=r"(r1), "=r"(r2), "=r"(r3) : "r"(a));
}

__device__ __forceinline__ void mma16816(float d[4], unsigned a0, unsigned a1, unsigned a2,
                                         unsigned a3, unsigned b0, unsigned b1) {
    asm volatile("mma.sync.aligned.m16n8k16.row.col.f32.bf16.bf16.f32 "
                 "{%0,%1,%2,%3},{%4,%5,%6,%7},{%8,%9},{%0,%1,%2,%3};"
                 : "+f"(d[0]), "+f"(d[1]), "+f"(d[2]), "+f"(d[3])
                 : "r"(a0), "r"(a1), "r"(a2), "r"(a3), "r"(b0), "r"(b1));
}

__device__ __forceinline__ float sigm(float v) {
    return __fdividef(1.f, 1.f + __expf(-v));
}
__device__ __forceinline__ float tanh_(float v) {
    float a = fabsf(v);
    float e = __expf(-2.f * a);
    float r = __fdividef(1.f - e, 1.f + e);
    return copysignf(r, v);
}

// gates[4 ntiles] += A(32x64 split) @ W(64x256 split), 3-product bf16 split.
__device__ __forceinline__ void gemm16(float acc[4][4], unsigned sb,
                                       unsigned aH, unsigned aL,
                                       unsigned wH, unsigned wL,
                                       unsigned raOff, unsigned cbOff) {
    #pragma unroll
    for (int ks = 0; ks < 4; ++ks) {
        unsigned ah0, ah1, ah2, ah3, al0, al1, al2, al3;
        ldsm4(ah0, ah1, ah2, ah3, sb + aH + swz(raOff + ks * 32));
        ldsm4(al0, al1, al2, al3, sb + aL + swz(raOff + ks * 32));
        #pragma unroll
        for (int tp = 0; tp < 2; ++tp) {
            unsigned bh0, bh1, bh2, bh3, bl0, bl1, bl2, bl3;
            ldsm4(bh0, bh1, bh2, bh3, sb + wH + swz(cbOff + tp * 2048 + ks * 32));
            ldsm4(bl0, bl1, bl2, bl3, sb + wL + swz(cbOff + tp * 2048 + ks * 32));
            mma16816(acc[2 * tp],     ah0, ah1, ah2, ah3, bh0, bh1);
            mma16816(acc[2 * tp],     ah0, ah1, ah2, ah3, bl0, bl1);
            mma16816(acc[2 * tp],     al0, al1, al2, al3, bh0, bh1);
            mma16816(acc[2 * tp + 1], ah0, ah1, ah2, ah3, bh2, bh3);
            mma16816(acc[2 * tp + 1], ah0, ah1, ah2, ah3, bl2, bl3);
            mma16816(acc[2 * tp + 1], al0, al1, al2, al3, bh2, bh3);
        }
    }
}

// Split LSTM cell: even lane (ifh=1) owns tiles 0,1; odd lane owns tiles 2,3.
// 8 shfl (exchange only). Outputs h for OWNED tiles: hvo[tt][row].
// cst[4] = c-state of owned tiles (2 tiles x 2 rows).
__device__ __forceinline__ void cellq2(const float acc[4][4], float cst[4],
                                       float hvo[2][2], int ifh) {
    float recv[2][4];
    #pragma unroll
    for (int tt = 0; tt < 2; ++tt)
        #pragma unroll
        for (int e = 0; e < 4; ++e) {
            // even sends acc[2+tt] (for odd's owned tiles); odd sends acc[tt]
            float send = ifh ? acc[2 + tt][e] : acc[tt][e];
            recv[tt][e] = __shfl_xor_sync(0xFFFFFFFFu, send, 1);
        }
    #pragma unroll
    for (int tt = 0; tt < 2; ++tt) {
        int t = ifh ? tt : 2 + tt;     // owned tile index
        // even lane: acc[t]=(i,f) rows A,B ; recv=(g,o). odd lane: swapped.
        float gi = ifh ? acc[t][0] : recv[tt][0];
        float gf = ifh ? acc[t][1] : recv[tt][1];
        float gg = ifh ? recv[tt][0] : acc[t][0];
        float go = ifh ? recv[tt][1] : acc[t][1];
        float cn = sigm(gf) * cst[2 * tt] + sigm(gi) * tanh_(gg);
        cst[2 * tt] = cn;
        hvo[tt][0] = sigm(go) * tanh_(cn);
        gi = ifh ? acc[t][2] : recv[tt][2];
        gf = ifh ? acc[t][3] : recv[tt][3];
        gg = ifh ? recv[tt][2] : acc[t][2];
        go = ifh ? recv[tt][3] : acc[t][3];
        cn = sigm(gf) * cst[2 * tt + 1] + sigm(gi) * tanh_(gg);
        cst[2 * tt + 1] = cn;
        hvo[tt][1] = sigm(go) * tanh_(cn);
    }
}

// Each lane stores h (bf16 hi/lo split) for its OWNED tiles: 8 stores/lane.
__device__ __forceinline__ void storehq(char *smp, unsigned offH, unsigned offL,
                                        const float hvo[2][2], int nb, int ug,
                                        int rA, int rB, int ifh) {
    #pragma unroll
    for (int tt = 0; tt < 2; ++tt) {
        int t = ifh ? tt : 2 + tt;
        int u = 2 * (nb + t) + ug;
        unsigned oA = swz((unsigned)(rA * 128 + u * 2));
        unsigned oB = swz((unsigned)(rB * 128 + u * 2));
        __nv_bfloat16 hA = __float2bfloat16(hvo[tt][0]);
        __nv_bfloat16 lA = __float2bfloat16(hvo[tt][0] - __bfloat162float(hA));
        __nv_bfloat16 hB = __float2bfloat16(hvo[tt][1]);
        __nv_bfloat16 lB = __float2bfloat16(hvo[tt][1] - __bfloat162float(hB));
        *(__nv_bfloat16 *)(smp + offH + oA) = hA;
        *(__nv_bfloat16 *)(smp + offL + oA) = lA;
        *(__nv_bfloat16 *)(smp + offH + oB) = hB;
        *(__nv_bfloat16 *)(smp + offL + oB) = lB;
    }
}

// Split-store raw fp32 weights [256 gate-rows][64 k] into gate-interleaved
// swizzled bf16 hi/lo: col c = u*4 + g, addr = swz(c*128 + k*2).
__device__ void store_w(char *smp, unsigned offH, unsigned offL, const float *__restrict__ raw) {
    for (int e = threadIdx.x; e < 256 * 64; e += NTH) {
        int R = e >> 6, k = e & 63;
        int c = (R & 63) * 4 + (R >> 6);
        float w = raw[e];
        __nv_bfloat16 hi = __float2bfloat16(w);
        __nv_bfloat16 lo = __float2bfloat16(w - __bfloat162float(hi));
        unsigned o = swz((unsigned)(c * 128 + k * 2));
        *(__nv_bfloat16 *)(smp + offH + o) = hi;
        *(__nv_bfloat16 *)(smp + offL + o) = lo;
    }
}

__global__ void __launch_bounds__(NTH, 1)
lstm_kernel(const float *__restrict__ x,
            const float *__restrict__ eWih0, const float *__restrict__ eWhh0,
            const float *__restrict__ eb0,
            const float *__restrict__ eWih1, const float *__restrict__ eWhh1,
            const float *__restrict__ eb1,
            const float *__restrict__ dWih0, const float *__restrict__ dWhh0,
            const float *__restrict__ db0,
            const float *__restrict__ dWih1, const float *__restrict__ dWhh1,
            const float *__restrict__ db1,
            const float *__restrict__ fcW, const float *__restrict__ fcb,
            float *__restrict__ out) {
    extern __shared__ char smem[];
    unsigned sb = (unsigned)__cvta_generic_to_shared(smem);

    const int tid = threadIdx.x;
    const int lane = tid & 31;
    const int wid = tid >> 5;
    const int mw = wid & 1;              // m-tile: rows 16mw..16mw+15
    const int nb = (wid >> 1) * 4;       // 4 n-tiles: cols 8nb..8nb+31
    const int blk = blockIdx.x;

    const int ifh = !(lane & 1);         // lane holds (i,f); partner holds (g,o)
    const int ug = (lane >> 1) & 1;      // unit-in-tile
    const int rA = mw * 16 + (lane >> 2);
    const int rB = rA + 8;

    // ldmatrix per-lane address bases (SW128-swizzled arrays, 128B row pitch)
    const unsigned raOff = (unsigned)((mw * 16 + (lane & 7) + (lane & 8)) * 128
                                      + ((lane >> 4) & 1) * 16);
    const unsigned cbOff = (unsigned)((8 * nb + (lane & 7) + 8 * ((lane >> 4) & 1)) * 128
                                      + ((lane >> 3) & 1) * 16);

    // tile gate columns for this lane (interleaved layout: c = u*4 + g)
    int cI[4][2];
    #pragma unroll
    for (int t = 0; t < 4; ++t) {
        int c0 = 8 * (nb + t) + ((lane & 3) << 1);
        cI[t][0] = (c0 & 3) * 64 + (c0 >> 2);          // raw gate-row index
        cI[t][1] = ((c0 + 1) & 3) * 64 + ((c0 + 1) >> 2);
    }

    // ---------- encoder weights ----------
    store_w(smem, OFF_W0H, OFF_W0L, eWhh0);
    store_w(smem, OFF_W1AH, OFF_W1AL, eWih1);
    store_w(smem, OFF_W1BH, OFF_W1BL, eWhh1);
    for (int i = tid; i < 8192; i += NTH) ((float *)(smem + OFF_AH0))[i] = 0.f;  // h bufs

    float b0c[4][2], b1c[4][2], wic[4][2];
    #pragma unroll
    for (int t = 0; t < 4; ++t) {
        b0c[t][0] = eb0[cI[t][0]]; b0c[t][1] = eb0[cI[t][1]];
        b1c[t][0] = eb1[cI[t][0]]; b1c[t][1] = eb1[cI[t][1]];
        wic[t][0] = eWih0[cI[t][0]]; wic[t][1] = eWih0[cI[t][1]];
    }
    __syncthreads();

    float c0s[4], c1s[4];
    #pragma unroll
    for (int i = 0; i < 4; ++i) { c0s[i] = 0.f; c1s[i] = 0.f; }

    const float *xrA = x + (blk * 32 + rA) * TT;
    const float *xrB = x + (blk * 32 + rB) * TT;
    float xA = xrA[0], xB = xrB[0];

    // ---------- encoder: 365 steps, 1 barrier/step ----------
    for (int t = 0; t < TT; ++t) {
        float xnA = (t + 1 < TT) ? xrA[t + 1] : 0.f;
        float xnB = (t + 1 < TT) ? xrB[t + 1] : 0.f;
        unsigned p = (unsigned)(t & 1);

        unsigned h0r = OFF_AH0 + p * 8192;            // [split 0 | split 1 (+4096)]
        unsigned h0w = OFF_AH0 + (p ^ 1) * 8192;
        unsigned h1r = OFF_AH1 + p * 8192;
        unsigned h1w = OFF_AH1 + (p ^ 1) * 8192;

        // layer 0: acc = b0 + x*wi ; += h0_prev @ Whh0
        float acc[4][4];
        #pragma unroll
        for (int tt = 0; tt < 4; ++tt) {
            acc[tt][0] = fmaf(xA, wic[tt][0], b0c[tt][0]);
            acc[tt][1] = fmaf(xA, wic[tt][1], b0c[tt][1]);
            acc[tt][2] = fmaf(xB, wic[tt][0], b0c[tt][0]);
            acc[tt][3] = fmaf(xB, wic[tt][1], b0c[tt][1]);
        }
        gemm16(acc, sb, h0r, h0r + 4096, OFF_W0H, OFF_W0L, raOff, cbOff);
        float hvo[2][2];
        cellq2(acc, c0s, hvo, ifh);
        storehq(smem, h0w, h0w + 4096, hvo, nb, ug, rA, rB, ifh);
        __syncthreads();

        // layer 1: acc = b1 ; += h0_cur @ Wih1 ; += h1_prev @ Whh1
        #pragma unroll
        for (int tt = 0; tt < 4; ++tt) {
            acc[tt][0] = b1c[tt][0]; acc[tt][1] = b1c[tt][1];
            acc[tt][2] = b1c[tt][0]; acc[tt][3] = b1c[tt][1];
        }
        gemm16(acc, sb, h0w, h0w + 4096, OFF_W1AH, OFF_W1AL, raOff, cbOff);
        gemm16(acc, sb, h1r, h1r + 4096, OFF_W1BH, OFF_W1BL, raOff, cbOff);
        cellq2(acc, c1s, hvo, ifh);
        storehq(smem, h1w, h1w + 4096, hvo, nb, ug, rA, rB, ifh);
        // no 2nd barrier: next step's barrier covers h1 visibility + WAR

        xA = xnA; xB = xnB;
    }
    __syncthreads();     // all encoder-weight reads done

    // ---------- decoder weights ----------
    store_w(smem, OFF_W0H, OFF_W0L, dWhh0);
    store_w(smem, OFF_W1AH, OFF_W1AL, dWih1);
    store_w(smem, OFF_W1BH, OFF_W1BL, dWhh1);
    float fcw2[2];
    #pragma unroll
    for (int t = 0; t < 4; ++t) {
        b0c[t][0] = db0[cI[t][0]]; b0c[t][1] = db0[cI[t][1]];
        b1c[t][0] = db1[cI[t][0]]; b1c[t][1] = db1[cI[t][1]];
        wic[t][0] = dWih0[cI[t][0]]; wic[t][1] = dWih0[cI[t][1]];
    }
    #pragma unroll
    for (int tt = 0; tt < 2; ++tt) {
        int t = ifh ? tt : 2 + tt;
        fcw2[tt] = fcW[2 * (nb + t) + ug];
    }
    const float fcbv = fcb[0];
    __syncthreads();

    // ---------- decoder: 7 autoregressive steps ----------
    xA = 0.f; xB = 0.f;
    for (int s = 0; s < HORIZON; ++s) {
        unsigned p = (unsigned)((TT + s) & 1);
        unsigned h0r = OFF_AH0 + p * 8192;
        unsigned h0w = OFF_AH0 + (p ^ 1) * 8192;
        unsigned h1r = OFF_AH1 + p * 8192;
        unsigned h1w = OFF_AH1 + (p ^ 1) * 8192;

        float acc[4][4];
        #pragma unroll
        for (int tt = 0; tt < 4; ++tt) {
            acc[tt][0] = fmaf(xA, wic[tt][0], b0c[tt][0]);
            acc[tt][1] = fmaf(xA, wic[tt][1], b0c[tt][1]);
            acc[tt][2] = fmaf(xB, wic[tt][0], b0c[tt][0]);
            acc[tt][3] = fmaf(xB, wic[tt][1], b0c[tt][1]);
        }
        gemm16(acc, sb, h0r, h0r + 4096, OFF_W0H, OFF_W0L, raOff, cbOff);
        float hvo[2][2];
        cellq2(acc, c0s, hvo, ifh);
        storehq(smem, h0w, h0w + 4096, hvo, nb, ug, rA, rB, ifh);
        __syncthreads();

        #pragma unroll
        for (int tt = 0; tt < 4; ++tt) {
            acc[tt][0] = b1c[tt][0]; acc[tt][1] = b1c[tt][1];
            acc[tt][2] = b1c[tt][0]; acc[tt][3] = b1c[tt][1];
        }
        gemm16(acc, sb, h0w, h0w + 4096, OFF_W1AH, OFF_W1AL, raOff, cbOff);
        gemm16(acc, sb, h1r, h1r + 4096, OFF_W1BH, OFF_W1BL, raOff, cbOff);
        cellq2(acc, c1s, hvo, ifh);
        storehq(smem, h1w, h1w + 4096, hvo, nb, ug, rA, rB, ifh);

        // FC: per-lane partial over OWNED tiles, reduce across quad (xor 1, 2)
        float v0 = hvo[0][0] * fcw2[0] + hvo[1][0] * fcw2[1];
        float v1 = hvo[0][1] * fcw2[0] + hvo[1][1] * fcw2[1];
        v0 += __shfl_xor_sync(0xFFFFFFFFu, v0, 1);
        v1 += __shfl_xor_sync(0xFFFFFFFFu, v1, 1);
        v0 += __shfl_xor_sync(0xFFFFFFFFu, v0, 2);
        v1 += __shfl_xor_sync(0xFFFFFFFFu, v1, 2);
        if ((lane & 3) == 0) {
            g_pp[blk][wid >> 1][rA] = v0;
            g_pp[blk][wid >> 1][rB] = v1;
        }
        __syncthreads();
        if (tid < 32) {
            float sum = fcbv;
            #pragma unroll
            for (int j = 0; j < 8; ++j) sum += g_pp[blk][j][tid];
            out[(blk * 32 + tid) * HORIZON + s] = sum;
            g_fb[blk][tid] = sum;
        }
        __syncthreads();
        xA = g_fb[blk][rA];
        xB = g_fb[blk][rB];
    }
}

extern "C" void kernel_launch(void *const *d_in, const int *in_sizes, int n_in,
                              void *d_out, int out_size) {
    cudaFuncSetAttribute(lstm_kernel, cudaFuncAttributeMaxDynamicSharedMemorySize, SMEM_BYTES);
    lstm_kernel<<<NCTA, NTH, SMEM_BYTES>>>(
        (const float *)d_in[0],
        (const float *)d_in[1], (const float *)d_in[2], (const float *)d_in[3],
        (const float *)d_in[4], (const float *)d_in[5], (const float *)d_in[6],
        (const float *)d_in[7], (const float *)d_in[8], (const float *)d_in[9],
        (const float *)d_in[10], (const float *)d_in[11], (const float *)d_in[12],
        (const float *)d_in[13], (const float *)d_in[14],
        (float *)d_out);
}

// round 12
// speedup vs baseline: 1.4462x; 1.0291x over previous
#include <cuda_runtime.h>
#include <cuda_bf16.h>

#define BB 4096
#define TT 365
#define HORIZON 7
#define NCTA 128
#define NTH 512

// ---- SMEM byte offsets (all arrays 128B-row pitch, SW128 swizzled) ----
#define OFF_W0H   0u          // Whh0 hi   [256 cols][64 k] bf16
#define OFF_W0L   32768u      // Whh0 lo
#define OFF_W1AH  65536u      // Wih1 hi   (L1, k from h0)
#define OFF_W1AL  98304u
#define OFF_W1BH  131072u     // Whh1 hi   (L1, k from h1)
#define OFF_W1BL  163840u
#define OFF_AH0   196608u     // h0[buf 2][split 2]: 32x64 bf16 = 4096B each
#define OFF_AH1   212992u     // h1[buf 2][split 2]
#define SMEM_BYTES 229376u

// decoder FC scratch (per-CTA slices of device globals; no allocation)
__device__ float g_pp[NCTA][8][32];
__device__ float g_fb[NCTA][32];

// Named barriers: A0/A1 (h0 published, parity), B0/B1 (h0 slot free, parity),
// D (L0-internal), C (L1-internal). Parity split bounds producer lead to 2
// steps so no barrier can be double-armed before its consumers sync.
#define BAR_SYNC(id, n)   asm volatile("bar.sync %0, %1;" :: "r"(id), "r"(n) : "memory")
#define BAR_ARRIVE(id, n) asm volatile("bar.arrive %0, %1;" :: "r"(id), "r"(n) : "memory")

__device__ __forceinline__ unsigned swz(unsigned o) { return o ^ ((o >> 3) & 0x70u); }

__device__ __forceinline__ void ldsm4(unsigned &r0, unsigned &r1, unsigned &r2, unsigned &r3,
                                      unsigned a) {
    asm volatile("ldmatrix.sync.aligned.m8n8.x4.shared.b16 {%0,%1,%2,%3}, [%4];"
                 : "=r"(r0), "=r"(r1), "=r"(r2), "=r"(r3) : "r"(a));
}

__device__ __forceinline__ void mma16816(float d[4], unsigned a0, unsigned a1, unsigned a2,
                                         unsigned a3, unsigned b0, unsigned b1) {
    asm volatile("mma.sync.aligned.m16n8k16.row.col.f32.bf16.bf16.f32 "
                 "{%0,%1,%2,%3},{%4,%5,%6,%7},{%8,%9},{%0,%1,%2,%3};"
                 : "+f"(d[0]), "+f"(d[1]), "+f"(d[2]), "+f"(d[3])
                 : "r"(a0), "r"(a1), "r"(a2), "r"(a3), "r"(b0), "r"(b1));
}

__device__ __forceinline__ float sigm(float v) {
    return __fdividef(1.f, 1.f + __expf(-v));
}
__device__ __forceinline__ float tanh_(float v) {
    float a = fabsf(v);
    float e = __expf(-2.f * a);
    float r = __fdividef(1.f - e, 1.f + e);
    return copysignf(r, v);
}

// gates += A(32x64 split) @ W(64x256 split), 3-product bf16 split.
// Warp tile m32 x n32: acc[mt][nt][4].
__device__ __forceinline__ void gemm32(float acc[2][4][4], unsigned sb,
                                       unsigned aH, unsigned aL,
                                       unsigned wH, unsigned wL,
                                       unsigned ra0, unsigned ra1, unsigned cbOff) {
    #pragma unroll
    for (int ks = 0; ks < 4; ++ks) {
        unsigned a0h[4], a0l[4], a1h[4], a1l[4];
        ldsm4(a0h[0], a0h[1], a0h[2], a0h[3], sb + aH + swz(ra0 + ks * 32));
        ldsm4(a0l[0], a0l[1], a0l[2], a0l[3], sb + aL + swz(ra0 + ks * 32));
        ldsm4(a1h[0], a1h[1], a1h[2], a1h[3], sb + aH + swz(ra1 + ks * 32));
        ldsm4(a1l[0], a1l[1], a1l[2], a1l[3], sb + aL + swz(ra1 + ks * 32));
        #pragma unroll
        for (int tp = 0; tp < 2; ++tp) {
            unsigned bh[4], bl[4];
            ldsm4(bh[0], bh[1], bh[2], bh[3], sb + wH + swz(cbOff + tp * 2048 + ks * 32));
            ldsm4(bl[0], bl[1], bl[2], bl[3], sb + wL + swz(cbOff + tp * 2048 + ks * 32));
            mma16816(acc[0][2 * tp],     a0h[0], a0h[1], a0h[2], a0h[3], bh[0], bh[1]);
            mma16816(acc[0][2 * tp],     a0h[0], a0h[1], a0h[2], a0h[3], bl[0], bl[1]);
            mma16816(acc[0][2 * tp],     a0l[0], a0l[1], a0l[2], a0l[3], bh[0], bh[1]);
            mma16816(acc[0][2 * tp + 1], a0h[0], a0h[1], a0h[2], a0h[3], bh[2], bh[3]);
            mma16816(acc[0][2 * tp + 1], a0h[0], a0h[1], a0h[2], a0h[3], bl[2], bl[3]);
            mma16816(acc[0][2 * tp + 1], a0l[0], a0l[1], a0l[2], a0l[3], bh[2], bh[3]);
            mma16816(acc[1][2 * tp],     a1h[0], a1h[1], a1h[2], a1h[3], bh[0], bh[1]);
            mma16816(acc[1][2 * tp],     a1h[0], a1h[1], a1h[2], a1h[3], bl[0], bl[1]);
            mma16816(acc[1][2 * tp],     a1l[0], a1l[1], a1l[2], a1l[3], bh[0], bh[1]);
            mma16816(acc[1][2 * tp + 1], a1h[0], a1h[1], a1h[2], a1h[3], bh[2], bh[3]);
            mma16816(acc[1][2 * tp + 1], a1h[0], a1h[1], a1h[2], a1h[3], bl[2], bl[3]);
            mma16816(acc[1][2 * tp + 1], a1l[0], a1l[1], a1l[2], a1l[3], bh[2], bh[3]);
        }
    }
}

// Split LSTM cell over one m16-tile-pair group: even lane owns nt 0,1; odd nt 2,3.
__device__ __forceinline__ void cellq2(const float acc[4][4], float cst[4],
                                       float hvo[2][2], int ifh) {
    float recv[2][4];
    #pragma unroll
    for (int tt = 0; tt < 2; ++tt)
        #pragma unroll
        for (int e = 0; e < 4; ++e) {
            float send = ifh ? acc[2 + tt][e] : acc[tt][e];
            recv[tt][e] = __shfl_xor_sync(0xFFFFFFFFu, send, 1);
        }
    #pragma unroll
    for (int tt = 0; tt < 2; ++tt) {
        int t = ifh ? tt : 2 + tt;
        float gi = ifh ? acc[t][0] : recv[tt][0];
        float gf = ifh ? acc[t][1] : recv[tt][1];
        float gg = ifh ? recv[tt][0] : acc[t][0];
        float go = ifh ? recv[tt][1] : acc[t][1];
        float cn = sigm(gf) * cst[2 * tt] + sigm(gi) * tanh_(gg);
        cst[2 * tt] = cn;
        hvo[tt][0] = sigm(go) * tanh_(cn);
        gi = ifh ? acc[t][2] : recv[tt][2];
        gf = ifh ? acc[t][3] : recv[tt][3];
        gg = ifh ? recv[tt][2] : acc[t][2];
        go = ifh ? recv[tt][3] : acc[t][3];
        cn = sigm(gf) * cst[2 * tt + 1] + sigm(gi) * tanh_(gg);
        cst[2 * tt + 1] = cn;
        hvo[tt][1] = sigm(go) * tanh_(cn);
    }
}

__device__ __forceinline__ void storehq(char *smp, unsigned offH, unsigned offL,
                                        const float hvo[2][2], int nb, int ug,
                                        int rA, int rB, int ifh) {
    #pragma unroll
    for (int tt = 0; tt < 2; ++tt) {
        int t = ifh ? tt : 2 + tt;
        int u = 2 * (nb + t) + ug;
        unsigned oA = swz((unsigned)(rA * 128 + u * 2));
        unsigned oB = swz((unsigned)(rB * 128 + u * 2));
        __nv_bfloat16 hA = __float2bfloat16(hvo[tt][0]);
        __nv_bfloat16 lA = __float2bfloat16(hvo[tt][0] - __bfloat162float(hA));
        __nv_bfloat16 hB = __float2bfloat16(hvo[tt][1]);
        __nv_bfloat16 lB = __float2bfloat16(hvo[tt][1] - __bfloat162float(hB));
        *(__nv_bfloat16 *)(smp + offH + oA) = hA;
        *(__nv_bfloat16 *)(smp + offL + oA) = lA;
        *(__nv_bfloat16 *)(smp + offH + oB) = hB;
        *(__nv_bfloat16 *)(smp + offL + oB) = lB;
    }
}

__device__ void store_w(char *smp, unsigned offH, unsigned offL, const float *__restrict__ raw) {
    for (int e = threadIdx.x; e < 256 * 64; e += NTH) {
        int R = e >> 6, k = e & 63;
        int c = (R & 63) * 4 + (R >> 6);
        float w = raw[e];
        __nv_bfloat16 hi = __float2bfloat16(w);
        __nv_bfloat16 lo = __float2bfloat16(w - __bfloat162float(hi));
        unsigned o = swz((unsigned)(c * 128 + k * 2));
        *(__nv_bfloat16 *)(smp + offH + o) = hi;
        *(__nv_bfloat16 *)(smp + offL + o) = lo;
    }
}

__global__ void __launch_bounds__(NTH, 1)
lstm_kernel(const float *__restrict__ x,
            const float *__restrict__ eWih0, const float *__restrict__ eWhh0,
            const float *__restrict__ eb0,
            const float *__restrict__ eWih1, const float *__restrict__ eWhh1,
            const float *__restrict__ eb1,
            const float *__restrict__ dWih0, const float *__restrict__ dWhh0,
            const float *__restrict__ db0,
            const float *__restrict__ dWih1, const float *__restrict__ dWhh1,
            const float *__restrict__ db1,
            const float *__restrict__ fcW, const float *__restrict__ fcb,
            float *__restrict__ out) {
    extern __shared__ char smem[];
    unsigned sb = (unsigned)__cvta_generic_to_shared(smem);

    const int tid = threadIdx.x;
    const int lane = tid & 31;
    const int wid = tid >> 5;
    const int jw = wid & 7;            // n-block: units 8jw..8jw+7
    const int nb = 4 * jw;             // first n8-tile index
    const int grp0 = (wid < 8);        // L0 group
    const int blk = blockIdx.x;

    const int ifh = !(lane & 1);
    const int ug = (lane >> 1) & 1;
    const int rA = lane >> 2;          // rows rA,rB (mt0) / +16 (mt1)
    const int rB = rA + 8;

    const unsigned ra0 = (unsigned)(((lane & 7) + (lane & 8)) * 128 + ((lane >> 4) & 1) * 16);
    const unsigned ra1 = ra0 + 16 * 128;
    const unsigned cbOff = (unsigned)((8 * nb + (lane & 7) + 8 * ((lane >> 4) & 1)) * 128
                                      + ((lane >> 3) & 1) * 16);

    // lane's 8 gate-columns (shared across mt): cI[nt][pair]
    int cI[4][2];
    #pragma unroll
    for (int t = 0; t < 4; ++t) {
        int c0 = 8 * (nb + t) + ((lane & 3) << 1);
        cI[t][0] = (c0 & 3) * 64 + (c0 >> 2);
        cI[t][1] = ((c0 + 1) & 3) * 64 + ((c0 + 1) >> 2);
    }

    // ---------- encoder weights ----------
    store_w(smem, OFF_W0H, OFF_W0L, eWhh0);
    store_w(smem, OFF_W1AH, OFF_W1AL, eWih1);
    store_w(smem, OFF_W1BH, OFF_W1BL, eWhh1);
    for (int i = tid; i < 8192; i += NTH) ((float *)(smem + OFF_AH0))[i] = 0.f;

    float bA[4][2], bB[4][2];          // grp0: b0, Wih0.  grp1: b1, (unused)
    #pragma unroll
    for (int t = 0; t < 4; ++t) {
        if (grp0) {
            bA[t][0] = eb0[cI[t][0]]; bA[t][1] = eb0[cI[t][1]];
            bB[t][0] = eWih0[cI[t][0]]; bB[t][1] = eWih0[cI[t][1]];
        } else {
            bA[t][0] = eb1[cI[t][0]]; bA[t][1] = eb1[cI[t][1]];
            bB[t][0] = 0.f; bB[t][1] = 0.f;
        }
    }
    __syncthreads();

    float cst[2][4];
    #pragma unroll
    for (int m = 0; m < 2; ++m)
        #pragma unroll
        for (int i = 0; i < 4; ++i) cst[m][i] = 0.f;

    // ================= encoder: warp-specialized pipeline =================
    if (grp0) {
        const float *xp0 = x + (blk * 32 + rA) * TT;
        const float *xp1 = x + (blk * 32 + rB) * TT;
        const float *xp2 = x + (blk * 32 + rA + 16) * TT;
        const float *xp3 = x + (blk * 32 + rB + 16) * TT;
        float xv[4] = {xp0[0], xp1[0], xp2[0], xp3[0]};
        for (int t = 0; t < TT; ++t) {
            float xn[4];
            xn[0] = (t + 1 < TT) ? xp0[t + 1] : 0.f;
            xn[1] = (t + 1 < TT) ? xp1[t + 1] : 0.f;
            xn[2] = (t + 1 < TT) ? xp2[t + 1] : 0.f;
            xn[3] = (t + 1 < TT) ? xp3[t + 1] : 0.f;

            float acc[2][4][4];
            #pragma unroll
            for (int m = 0; m < 2; ++m)
                #pragma unroll
                for (int tt = 0; tt < 4; ++tt) {
                    acc[m][tt][0] = fmaf(xv[2 * m],     bB[tt][0], bA[tt][0]);
                    acc[m][tt][1] = fmaf(xv[2 * m],     bB[tt][1], bA[tt][1]);
                    acc[m][tt][2] = fmaf(xv[2 * m + 1], bB[tt][0], bA[tt][0]);
                    acc[m][tt][3] = fmaf(xv[2 * m + 1], bB[tt][1], bA[tt][1]);
                }
            unsigned h0r = OFF_AH0 + (unsigned)(t & 1) * 8192u;
            unsigned h0w = OFF_AH0 + (unsigned)((t + 1) & 1) * 8192u;
            gemm32(acc, sb, h0r, h0r + 4096, OFF_W0H, OFF_W0L, ra0, ra1, cbOff);
            float hv0[2][2], hv1[2][2];
            cellq2(acc[0], cst[0], hv0, ifh);
            cellq2(acc[1], cst[1], hv1, ifh);
            BAR_SYNC(3 + (t & 1), 512);                 // slot free (L1 read h0(t-2))
            storehq(smem, h0w, h0w + 4096, hv0, nb, ug, rA, rB, ifh);
            storehq(smem, h0w, h0w + 4096, hv1, nb, ug, rA + 16, rB + 16, ifh);
            BAR_SYNC(5, 256);                           // L0-internal visibility
            BAR_ARRIVE(1 + (t & 1), 512);               // publish h0(t)
            xv[0] = xn[0]; xv[1] = xn[1]; xv[2] = xn[2]; xv[3] = xn[3];
        }
    } else {
        BAR_ARRIVE(3, 512);                             // pre-charge slot-free (t=0,1)
        BAR_ARRIVE(4, 512);
        for (int s = 0; s < TT; ++s) {
            float acc[2][4][4];
            #pragma unroll
            for (int m = 0; m < 2; ++m)
                #pragma unroll
                for (int tt = 0; tt < 4; ++tt) {
                    acc[m][tt][0] = bA[tt][0]; acc[m][tt][1] = bA[tt][1];
                    acc[m][tt][2] = bA[tt][0]; acc[m][tt][3] = bA[tt][1];
                }
            unsigned h1r = OFF_AH1 + (unsigned)(s & 1) * 8192u;
            unsigned h1w = OFF_AH1 + (unsigned)((s + 1) & 1) * 8192u;
            unsigned h0c = OFF_AH0 + (unsigned)((s + 1) & 1) * 8192u;   // h0(s)
            gemm32(acc, sb, h1r, h1r + 4096, OFF_W1BH, OFF_W1BL, ra0, ra1, cbOff);
            BAR_SYNC(1 + (s & 1), 512);                 // wait h0(s)
            gemm32(acc, sb, h0c, h0c + 4096, OFF_W1AH, OFF_W1AL, ra0, ra1, cbOff);
            BAR_ARRIVE(3 + (s & 1), 512);               // done reading h0(s)
            float hv0[2][2], hv1[2][2];
            cellq2(acc[0], cst[0], hv0, ifh);
            cellq2(acc[1], cst[1], hv1, ifh);
            storehq(smem, h1w, h1w + 4096, hv0, nb, ug, rA, rB, ifh);
            storehq(smem, h1w, h1w + 4096, hv1, nb, ug, rA + 16, rB + 16, ifh);
            BAR_SYNC(6, 256);                           // L1-internal visibility
        }
    }
    __syncthreads();

    // ---------- decoder weights ----------
    store_w(smem, OFF_W0H, OFF_W0L, dWhh0);
    store_w(smem, OFF_W1AH, OFF_W1AL, dWih1);
    store_w(smem, OFF_W1BH, OFF_W1BL, dWhh1);
    float fcw2[2] = {0.f, 0.f};
    #pragma unroll
    for (int t = 0; t < 4; ++t) {
        if (grp0) {
            bA[t][0] = db0[cI[t][0]]; bA[t][1] = db0[cI[t][1]];
            bB[t][0] = dWih0[cI[t][0]]; bB[t][1] = dWih0[cI[t][1]];
        } else {
            bA[t][0] = db1[cI[t][0]]; bA[t][1] = db1[cI[t][1]];
        }
    }
    if (!grp0) {
        #pragma unroll
        for (int tt = 0; tt < 2; ++tt) {
            int t = ifh ? tt : 2 + tt;
            fcw2[tt] = fcW[2 * (nb + t) + ug];
        }
    }
    const float fcbv = fcb[0];
    __syncthreads();

    // ---------- decoder: 7 steps, common path, group-gated ----------
    float din[4] = {0.f, 0.f, 0.f, 0.f};
    for (int s = 0; s < HORIZON; ++s) {
        unsigned rp = (unsigned)((TT + s) & 1);
        unsigned h0r = OFF_AH0 + rp * 8192u, h0w = OFF_AH0 + (rp ^ 1) * 8192u;
        unsigned h1r = OFF_AH1 + rp * 8192u, h1w = OFF_AH1 + (rp ^ 1) * 8192u;

        if (grp0) {
            float acc[2][4][4];
            #pragma unroll
            for (int m = 0; m < 2; ++m)
                #pragma unroll
                for (int tt = 0; tt < 4; ++tt) {
                    acc[m][tt][0] = fmaf(din[2 * m],     bB[tt][0], bA[tt][0]);
                    acc[m][tt][1] = fmaf(din[2 * m],     bB[tt][1], bA[tt][1]);
                    acc[m][tt][2] = fmaf(din[2 * m + 1], bB[tt][0], bA[tt][0]);
                    acc[m][tt][3] = fmaf(din[2 * m + 1], bB[tt][1], bA[tt][1]);
                }
            gemm32(acc, sb, h0r, h0r + 4096, OFF_W0H, OFF_W0L, ra0, ra1, cbOff);
            float hv0[2][2], hv1[2][2];
            cellq2(acc[0], cst[0], hv0, ifh);
            cellq2(acc[1], cst[1], hv1, ifh);
            storehq(smem, h0w, h0w + 4096, hv0, nb, ug, rA, rB, ifh);
            storehq(smem, h0w, h0w + 4096, hv1, nb, ug, rA + 16, rB + 16, ifh);
        }
        __syncthreads();
        if (!grp0) {
            float acc[2][4][4];
            #pragma unroll
            for (int m = 0; m < 2; ++m)
                #pragma unroll
                for (int tt = 0; tt < 4; ++tt) {
                    acc[m][tt][0] = bA[tt][0]; acc[m][tt][1] = bA[tt][1];
                    acc[m][tt][2] = bA[tt][0]; acc[m][tt][3] = bA[tt][1];
                }
            gemm32(acc, sb, h1r, h1r + 4096, OFF_W1BH, OFF_W1BL, ra0, ra1, cbOff);
            gemm32(acc, sb, h0w, h0w + 4096, OFF_W1AH, OFF_W1AL, ra0, ra1, cbOff);
            float hv0[2][2], hv1[2][2];
            cellq2(acc[0], cst[0], hv0, ifh);
            cellq2(acc[1], cst[1], hv1, ifh);
            storehq(smem, h1w, h1w + 4096, hv0, nb, ug, rA, rB, ifh);
            storehq(smem, h1w, h1w + 4096, hv1, nb, ug, rA + 16, rB + 16, ifh);
            float v00 = hv0[0][0] * fcw2[0] + hv0[1][0] * fcw2[1];
            float v01 = hv0[0][1] * fcw2[0] + hv0[1][1] * fcw2[1];
            float v10 = hv1[0][0] * fcw2[0] + hv1[1][0] * fcw2[1];
            float v11 = hv1[0][1] * fcw2[0] + hv1[1][1] * fcw2[1];
            v00 += __shfl_xor_sync(0xFFFFFFFFu, v00, 1);
            v01 += __shfl_xor_sync(0xFFFFFFFFu, v01, 1);
            v10 += __shfl_xor_sync(0xFFFFFFFFu, v10, 1);
            v11 += __shfl_xor_sync(0xFFFFFFFFu, v11, 1);
            v00 += __shfl_xor_sync(0xFFFFFFFFu, v00, 2);
            v01 += __shfl_xor_sync(0xFFFFFFFFu, v01, 2);
            v10 += __shfl_xor_sync(0xFFFFFFFFu, v10, 2);
            v11 += __shfl_xor_sync(0xFFFFFFFFu, v11, 2);
            if ((lane & 3) == 0) {
                g_pp[blk][jw][rA] = v00;
                g_pp[blk][jw][rB] = v01;
                g_pp[blk][jw][rA + 16] = v10;
                g_pp[blk][jw][rB + 16] = v11;
            }
        }
        __syncthreads();
        if (tid < 32) {
            float sum = fcbv;
            #pragma unroll
            for (int j = 0; j < 8; ++j) sum += g_pp[blk][j][tid];
            out[(blk * 32 + tid) * HORIZON + s] = sum;
            g_fb[blk][tid] = sum;
        }
        __syncthreads();
        if (grp0) {
            din[0] = g_fb[blk][rA];
            din[1] = g_fb[blk][rB];
            din[2] = g_fb[blk][rA + 16];
            din[3] = g_fb[blk][rB + 16];
        }
    }
}

extern "C" void kernel_launch(void *const *d_in, const int *in_sizes, int n_in,
                              void *d_out, int out_size) {
    cudaFuncSetAttribute(lstm_kernel, cudaFuncAttributeMaxDynamicSharedMemorySize, SMEM_BYTES);
    lstm_kernel<<<NCTA, NTH, SMEM_BYTES>>>(
        (const float *)d_in[0],
        (const float *)d_in[1], (const float *)d_in[2], (const float *)d_in[3],
        (const float *)d_in[4], (const float *)d_in[5], (const float *)d_in[6],
        (const float *)d_in[7], (const float *)d_in[8], (const float *)d_in[9],
        (const float *)d_in[10], (const float *)d_in[11], (const float *)d_in[12],
        (const float *)d_in[13], (const float *)d_in[14],
        (float *)d_out);
}